// round 12
// baseline (speedup 1.0000x reference)
#include <cuda_runtime.h>
#include <cuda_fp16.h>
#include <cstdint>

// ---------------- problem constants ----------------
#define C_IN   256
#define HDIM   56
#define WDIM   56
#define HW     3136
#define HP     58
#define PP     (HP * HP)          // 3364 padded positions
#define OCH    256
#define KTOT   2304               // reordered: k' = tap*256 + c
#define M_TOT  100352

// ---------------- GEMM config ----------------
#define BM     128
#define BN     128
#define BK     32
#define NTHREADS 256
#define KCH    (KTOT / BK)        // 72 chunks; 8 per tap
// swizzled rows: 32 halves = 64B = 4 granules of 16B, phys g = g ^ ((row>>1)&3)
#define A_ST_B 8192               // 128 rows * 64B
#define STG_B  16384              // A + B per stage
#define NSTAGE 6
#define SMEM_BYTES (NSTAGE * STG_B)   // 98304

// ---------------- device scratch ----------------
__device__ __align__(16) __half d_Xp[32 * PP * C_IN];   // halo-padded, [n][p][c] fp16
__device__ __align__(16) __half d_Wq[OCH * KTOT];       // [o][tap*256+c], exact fp16
__device__ float d_S[M_TOT];                            // channel sums
__device__ float d_R[M_TOT];                            // 3x3 window sums

// ---------------- helpers ----------------
__device__ __forceinline__ uint32_t smem_u32(const void* p) {
    uint32_t a;
    asm("{ .reg .u64 t; cvta.to.shared.u64 t, %1; cvt.u32.u64 %0, t; }" : "=r"(a) : "l"(p));
    return a;
}
__device__ __forceinline__ uint32_t swz(uint32_t row, uint32_t g) {
    return row * 64u + ((g ^ ((row >> 1) & 3u)) * 16u);
}
__device__ __forceinline__ void ldmatrix_x4(uint32_t& r0, uint32_t& r1, uint32_t& r2,
                                            uint32_t& r3, uint32_t addr) {
    asm volatile("ldmatrix.sync.aligned.m8n8.x4.shared.b16 {%0,%1,%2,%3}, [%4];"
                 : "=r"(r0), "=r"(r1), "=r"(r2), "=r"(r3) : "r"(addr));
}
__device__ __forceinline__ void mma16816(float* c, uint32_t a0, uint32_t a1, uint32_t a2,
                                         uint32_t a3, uint32_t b0, uint32_t b1) {
    asm volatile(
        "mma.sync.aligned.m16n8k16.row.col.f32.f16.f16.f32 "
        "{%0,%1,%2,%3}, {%4,%5,%6,%7}, {%8,%9}, {%0,%1,%2,%3};"
        : "+f"(c[0]), "+f"(c[1]), "+f"(c[2]), "+f"(c[3])
        : "r"(a0), "r"(a1), "r"(a2), "r"(a3), "r"(b0), "r"(b1));
}
__device__ __forceinline__ void cp_async16(uint32_t saddr, const void* gaddr) {
    asm volatile("cp.async.cg.shared.global [%0], [%1], 16;" :: "r"(saddr), "l"(gaddr));
}

// ---------------- fused prep kernel ----------------
// blocks [0, XPREP_BLOCKS):                     x -> d_Xp (halo-padded fp16)
// blocks [XPREP_BLOCKS, +WPREP_BLOCKS):         q -> d_Wq (reordered fp16)
// blocks [.., +SSUM_BLOCKS):                    x -> d_S  (channel sums, fp32)
#define XPREP_BLOCKS (32 * HP * (C_IN / 32))        // 14848
#define WPREP_BLOCKS ((OCH * KTOT) / 256)           // 2304
#define SSUM_BLOCKS  ((M_TOT + 255) / 256)          // 392
__global__ void qc_prep(const float* __restrict__ x, const int* __restrict__ q) {
    __shared__ float tile[32][57];
    const int bid = blockIdx.x;
    const int tid = threadIdx.x;

    if (bid < XPREP_BLOCKS) {
        // ---- xprep: x [n][c][h][w] fp32 -> d_Xp [n][(h+1)*58+(w+1)][c] fp16 ----
        const int n    = bid & 31;
        const int rest = bid >> 5;
        const int hp   = rest % HP;          // 0..57
        const int c0   = (rest / HP) * 32;
        const int tx   = tid & 31;
        const int ty   = tid >> 5;           // 0..7
        const bool hin = (hp >= 1) && (hp <= HDIM);

        if (hin) {
            const int h = hp - 1;
            const float* src = x + ((size_t)n * C_IN) * HW + h * WDIM;
#pragma unroll
            for (int i = 0; i < 4; i++) {
                int c = ty + 8 * i;
                const float* row = src + (size_t)(c0 + c) * HW;
                tile[c][tx] = row[tx];
                if (tx < WDIM - 32) tile[c][tx + 32] = row[tx + 32];
            }
        }
        __syncthreads();

        __half* dst = d_Xp + ((size_t)n * PP + (size_t)hp * HP) * C_IN + c0 + tx;
#pragma unroll
        for (int j = 0; j < 8; j++) {
            int wp = ty + 8 * j;
            if (wp < HP) {
                float v = 0.f;
                if (hin && wp >= 1 && wp <= WDIM) v = tile[tx][wp - 1];
                dst[(size_t)wp * C_IN] = __float2half_rn(v);
            }
        }
    } else if (bid < XPREP_BLOCKS + WPREP_BLOCKS) {
        // ---- wprep: q [o][c*9+tap] -> d_Wq [o][tap*256+c] (exact fp16) ----
        const int idx = (bid - XPREP_BLOCKS) * 256 + tid;
        const int o   = idx / KTOT;
        const int ks  = idx - o * KTOT;
        const int c   = ks / 9;
        const int tap = ks - c * 9;
        d_Wq[o * KTOT + tap * 256 + c] = __int2half_rn(q[idx]);
    } else {
        // ---- ssum: per-position channel sums (fp32, strided) ----
        const int m = (bid - XPREP_BLOCKS - WPREP_BLOCKS) * 256 + tid;
        if (m < M_TOT) {
            const int n  = m / HW;
            const int hw = m - n * HW;
            const float* p = x + (size_t)n * C_IN * HW + hw;
            float s = 0.f;
#pragma unroll 8
            for (int c = 0; c < C_IN; c++) s += p[(size_t)c * HW];
            d_S[m] = s;
        }
    }
}

__global__ void qc_rsum() {
    int m = blockIdx.x * blockDim.x + threadIdx.x;
    if (m >= M_TOT) return;
    int n  = m / HW;
    int hw = m - n * HW;
    int h  = hw / WDIM;
    int w  = hw - h * WDIM;
    const float* base = d_S + (size_t)n * HW;
    float acc = 0.f;
#pragma unroll
    for (int kh = 0; kh < 3; kh++)
#pragma unroll
        for (int kw = 0; kw < 3; kw++) {
            int hh = h + kh - 1, ww = w + kw - 1;
            if ((unsigned)hh < HDIM && (unsigned)ww < WDIM)
                acc += base[hh * WDIM + ww];
        }
    d_R[m] = acc;
}

// ---------------- main fp16 mma.sync implicit-GEMM kernel (R9 best) ----------------
// CTA 128x128; 8 warps as 2(M) x 4(N), each 64x32.
// Swizzled smem, 6-stage cp.async, ONE barrier per TWO chunks, warp staggering.
__global__ __launch_bounds__(NTHREADS, 2)
void qc_mma_kernel(const float* __restrict__ wscale,
                   const float* __restrict__ wmin,
                   const float* __restrict__ bias,
                   float* __restrict__ out) {
    extern __shared__ __half smem[];
    const uint32_t s0 = smem_u32(smem);

    const int tid  = threadIdx.x;
    const int lane = tid & 31;
    const int wid  = tid >> 5;
    const int bm   = blockIdx.x;
    const int bn   = blockIdx.y;

    // ---- producers: row = tid>>1, logical granules g0,g0+1 ----
    const int arow = tid >> 1;
    const int g0   = (tid & 1) * 2;
    const int m    = bm * BM + arow;
    const int n_i  = m / HW;
    const int hw   = m - n_i * HW;
    const int h    = hw / WDIM;
    const int w    = hw - h * WDIM;
    const size_t abase = ((size_t)n_i * PP + (size_t)h * HP + w);   // (kh=0,kw=0)
    const uint32_t adst0 = s0 + swz(arow, g0);
    const uint32_t adst1 = s0 + swz(arow, g0 + 1);
    const __half* bsrc0 = d_Wq + (size_t)(bn * BN + arow) * KTOT + g0 * 8;
    const uint32_t bdst0 = s0 + A_ST_B + swz(arow, g0);
    const uint32_t bdst1 = s0 + A_ST_B + swz(arow, g0 + 1);

    // ---- compute mapping: 2(M) x 4(N) warps, each 64x32 ----
    const int warp_m = wid >> 2;
    const int warp_n = wid & 3;

    uint32_t aoff[4][2], boff[2][2];
#pragma unroll
    for (int mt = 0; mt < 4; mt++)
#pragma unroll
        for (int ks = 0; ks < 2; ks++) {
            uint32_t row = warp_m * 64 + mt * 16 + (lane & 15);
            uint32_t g   = ks * 2 + (lane >> 4);
            aoff[mt][ks] = swz(row, g);
        }
#pragma unroll
    for (int nt2 = 0; nt2 < 2; nt2++)
#pragma unroll
        for (int ks = 0; ks < 2; ks++) {
            uint32_t row = warp_n * 32 + nt2 * 16 + ((lane >> 4) << 3) + (lane & 7);
            uint32_t g   = ks * 2 + ((lane >> 3) & 1);
            boff[nt2][ks] = A_ST_B + swz(row, g);
        }

    float acc[4][4][4];
#pragma unroll
    for (int i = 0; i < 4; i++)
#pragma unroll
        for (int j = 0; j < 4; j++)
#pragma unroll
            for (int r = 0; r < 4; r++) acc[i][j][r] = 0.f;

    auto issue = [&](int kt, int st) {
        const int tap   = kt >> 3;
        const int kh    = (tap * 11) >> 5;          // tap/3 for 0..8
        const int kw    = tap - 3 * kh;
        const int cbase = (kt & 7) * 32;
        const uint32_t soff = (uint32_t)st * STG_B;
        const __half* ga = d_Xp + (abase + kh * HP + kw) * C_IN + cbase + g0 * 8;
        cp_async16(adst0 + soff, ga);
        cp_async16(adst1 + soff, ga + 8);
        const __half* gb = bsrc0 + kt * BK;
        cp_async16(bdst0 + soff, gb);
        cp_async16(bdst1 + soff, gb + 8);
        asm volatile("cp.async.commit_group;");
    };

    const int ksrot = (wid >> 1) & 1;
    auto compute = [&](int st) {
        const uint32_t soff = (uint32_t)st * STG_B;
#pragma unroll
        for (int ksi = 0; ksi < 2; ksi++) {
            const int ks = ksi ^ ksrot;
            uint32_t a[4][4], b[2][4];
#pragma unroll
            for (int mt = 0; mt < 4; mt++)
                ldmatrix_x4(a[mt][0], a[mt][1], a[mt][2], a[mt][3],
                            s0 + soff + aoff[mt][ks]);
#pragma unroll
            for (int nt2 = 0; nt2 < 2; nt2++)
                ldmatrix_x4(b[nt2][0], b[nt2][1], b[nt2][2], b[nt2][3],
                            s0 + soff + boff[nt2][ks]);
#pragma unroll
            for (int mt = 0; mt < 4; mt++) {
#pragma unroll
                for (int nt = 0; nt < 4; nt++) {
                    uint32_t b0 = b[nt >> 1][(nt & 1) * 2];
                    uint32_t b1 = b[nt >> 1][(nt & 1) * 2 + 1];
                    mma16816(acc[mt][nt], a[mt][0], a[mt][1], a[mt][2], a[mt][3], b0, b1);
                }
            }
        }
    };

    // ---- prologue: fill 4 stages ----
    issue(0, 0);
    issue(1, 1);
    issue(2, 2);
    issue(3, 3);

    // ---- mainloop: per iteration handle chunk pair (kt, kt+1) ----
    const int chswap = wid & 1;
    int st = 0;
#pragma unroll 1
    for (int kt = 0; kt < KCH; kt += 2) {
        asm volatile("cp.async.wait_group 2;" ::: "memory");
        __syncthreads();
        {
            int s4 = st + 4; if (s4 >= NSTAGE) s4 -= NSTAGE;
            int s5 = st + 5; if (s5 >= NSTAGE) s5 -= NSTAGE;
            if (kt + 4 < KCH) issue(kt + 4, s4);
            else asm volatile("cp.async.commit_group;");
            if (kt + 5 < KCH) issue(kt + 5, s5);
            else asm volatile("cp.async.commit_group;");
        }
        {
            int s1 = st + 1; if (s1 >= NSTAGE) s1 -= NSTAGE;
            if (chswap) { compute(s1); compute(st); }
            else        { compute(st); compute(s1); }
        }
        st += 2; if (st >= NSTAGE) st -= NSTAGE;
    }

    // ---- epilogue: out = s*acc + mn*R[m] + bias[o] ----
    const float s  = __ldg(wscale);
    const float mn = __ldg(wmin);
    const int g  = lane >> 2;
    const int qd = (lane & 3) * 2;
#pragma unroll
    for (int mt = 0; mt < 4; mt++) {
#pragma unroll
        for (int hh2 = 0; hh2 < 2; hh2++) {
            const int mloc = warp_m * 64 + mt * 16 + g + 8 * hh2;
            const int mo   = bm * BM + mloc;
            const int n2   = mo / HW;
            const int hw2  = mo - n2 * HW;
            const float bm_ = mn * d_R[mo];
            float* op = out + (size_t)n2 * OCH * HW + hw2;
#pragma unroll
            for (int nt = 0; nt < 4; nt++) {
                const int o0 = bn * BN + warp_n * 32 + nt * 8 + qd;
                op[(size_t)o0 * HW] =
                    fmaf(s, acc[mt][nt][hh2 * 2],     bm_ + __ldg(&bias[o0]));
                op[(size_t)(o0 + 1) * HW] =
                    fmaf(s, acc[mt][nt][hh2 * 2 + 1], bm_ + __ldg(&bias[o0 + 1]));
            }
        }
    }
}

// ---------------- launch ----------------
extern "C" void kernel_launch(void* const* d_in, const int* in_sizes, int n_in,
                              void* d_out, int out_size) {
    const float* x      = (const float*)d_in[0];
    const int*   q      = (const int*)  d_in[1];
    const float* wscale = (const float*)d_in[2];
    const float* wmin   = (const float*)d_in[3];
    const float* bias   = (const float*)d_in[4];
    float*       out    = (float*)d_out;

    // 3 launches: fused prep -> rsum -> mma (mma in top-3 profiled)
    qc_prep<<<XPREP_BLOCKS + WPREP_BLOCKS + SSUM_BLOCKS, 256>>>(x, q);
    qc_rsum<<<(M_TOT + 255) / 256, 256>>>();

    cudaFuncSetAttribute(qc_mma_kernel,
                         cudaFuncAttributeMaxDynamicSharedMemorySize, SMEM_BYTES);
    dim3 grid(M_TOT / BM, OCH / BN);     // (784, 2)
    qc_mma_kernel<<<grid, NTHREADS, SMEM_BYTES>>>(wscale, wmin, bias, out);
}

// round 13
// speedup vs baseline: 1.0780x; 1.0780x over previous
#include <cuda_runtime.h>
#include <cuda_fp16.h>
#include <cstdint>

// ---------------- problem constants ----------------
#define C_IN   256
#define HDIM   56
#define WDIM   56
#define HW     3136
#define HP     58
#define PP     (HP * HP)          // 3364 padded positions
#define OCH    256
#define KTOT   2304               // reordered: k' = tap*256 + c
#define M_TOT  100352

// ---------------- GEMM config ----------------
#define BM     128
#define BN     128
#define BK     32
#define NTHREADS 256
#define KCH    (KTOT / BK)        // 72 chunks; 8 per tap
// swizzled rows: 32 halves = 64B = 4 granules of 16B, phys g = g ^ ((row>>1)&3)
#define A_ST_B 8192               // 128 rows * 64B
#define STG_B  16384              // A + B per stage
#define NSTAGE 6
#define SMEM_BYTES (NSTAGE * STG_B)   // 98304

// ---------------- device scratch ----------------
__device__ __align__(16) __half d_Xp[32 * PP * C_IN];   // halo-padded, [n][p][c] fp16
__device__ __align__(16) __half d_Ww[OCH * KTOT];       // [o][tap*256+c], w=q*s+min fp16

// ---------------- helpers ----------------
__device__ __forceinline__ uint32_t smem_u32(const void* p) {
    uint32_t a;
    asm("{ .reg .u64 t; cvta.to.shared.u64 t, %1; cvt.u32.u64 %0, t; }" : "=r"(a) : "l"(p));
    return a;
}
__device__ __forceinline__ uint32_t swz(uint32_t row, uint32_t g) {
    return row * 64u + ((g ^ ((row >> 1) & 3u)) * 16u);
}
__device__ __forceinline__ void ldmatrix_x4(uint32_t& r0, uint32_t& r1, uint32_t& r2,
                                            uint32_t& r3, uint32_t addr) {
    asm volatile("ldmatrix.sync.aligned.m8n8.x4.shared.b16 {%0,%1,%2,%3}, [%4];"
                 : "=r"(r0), "=r"(r1), "=r"(r2), "=r"(r3) : "r"(addr));
}
__device__ __forceinline__ void mma16816(float* c, uint32_t a0, uint32_t a1, uint32_t a2,
                                         uint32_t a3, uint32_t b0, uint32_t b1) {
    asm volatile(
        "mma.sync.aligned.m16n8k16.row.col.f32.f16.f16.f32 "
        "{%0,%1,%2,%3}, {%4,%5,%6,%7}, {%8,%9}, {%0,%1,%2,%3};"
        : "+f"(c[0]), "+f"(c[1]), "+f"(c[2]), "+f"(c[3])
        : "r"(a0), "r"(a1), "r"(a2), "r"(a3), "r"(b0), "r"(b1));
}
__device__ __forceinline__ void cp_async16(uint32_t saddr, const void* gaddr) {
    asm volatile("cp.async.cg.shared.global [%0], [%1], 16;" :: "r"(saddr), "l"(gaddr));
}

// ---------------- fused prep kernel ----------------
// blocks [0, XPREP_BLOCKS):            x -> d_Xp (halo-padded fp16)
// blocks [XPREP_BLOCKS, +WPREP):       q -> d_Ww = q*s + min (reordered fp16)
#define XPREP_BLOCKS (32 * HP * (C_IN / 32))        // 14848
#define WPREP_BLOCKS ((OCH * KTOT) / 256)           // 2304
__global__ void qc_prep(const float* __restrict__ x, const int* __restrict__ q,
                        const float* __restrict__ wscale,
                        const float* __restrict__ wmin) {
    __shared__ float tile[32][57];
    const int bid = blockIdx.x;
    const int tid = threadIdx.x;

    if (bid < XPREP_BLOCKS) {
        // ---- xprep: x [n][c][h][w] fp32 -> d_Xp [n][(h+1)*58+(w+1)][c] fp16 ----
        const int n    = bid & 31;
        const int rest = bid >> 5;
        const int hp   = rest % HP;          // 0..57
        const int c0   = (rest / HP) * 32;
        const int tx   = tid & 31;
        const int ty   = tid >> 5;           // 0..7
        const bool hin = (hp >= 1) && (hp <= HDIM);

        if (hin) {
            const int h = hp - 1;
            const float* src = x + ((size_t)n * C_IN) * HW + h * WDIM;
#pragma unroll
            for (int i = 0; i < 4; i++) {
                int c = ty + 8 * i;
                const float* row = src + (size_t)(c0 + c) * HW;
                tile[c][tx] = row[tx];
                if (tx < WDIM - 32) tile[c][tx + 32] = row[tx + 32];
            }
        }
        __syncthreads();

        __half* dst = d_Xp + ((size_t)n * PP + (size_t)hp * HP) * C_IN + c0 + tx;
#pragma unroll
        for (int j = 0; j < 8; j++) {
            int wp = ty + 8 * j;
            if (wp < HP) {
                float v = 0.f;
                if (hin && wp >= 1 && wp <= WDIM) v = tile[tx][wp - 1];
                dst[(size_t)wp * C_IN] = __float2half_rn(v);
            }
        }
    } else {
        // ---- wprep: q [o][c*9+tap] -> d_Ww [o][tap*256+c] = q*s+min (fp16) ----
        const float s  = __ldg(wscale);
        const float mn = __ldg(wmin);
        const int idx = (bid - XPREP_BLOCKS) * 256 + tid;
        const int o   = idx / KTOT;
        const int ks  = idx - o * KTOT;
        const int c   = ks / 9;
        const int tap = ks - c * 9;
        d_Ww[o * KTOT + tap * 256 + c] =
            __float2half_rn(fmaf((float)q[idx], s, mn));
    }
}

// ---------------- main fp16 mma.sync implicit-GEMM kernel (R9 mainloop) ----------
// CTA 128x128; 8 warps as 2(M) x 4(N), each 64x32.
// Swizzled smem, 6-stage cp.async, ONE barrier per TWO chunks, warp staggering.
// out = X @ Ww^T + bias  (affine already folded into Ww)
__global__ __launch_bounds__(NTHREADS, 2)
void qc_mma_kernel(const float* __restrict__ bias,
                   float* __restrict__ out) {
    extern __shared__ __half smem[];
    const uint32_t s0 = smem_u32(smem);

    const int tid  = threadIdx.x;
    const int lane = tid & 31;
    const int wid  = tid >> 5;
    const int bm   = blockIdx.x;
    const int bn   = blockIdx.y;

    // ---- producers: row = tid>>1, logical granules g0,g0+1 ----
    const int arow = tid >> 1;
    const int g0   = (tid & 1) * 2;
    const int m    = bm * BM + arow;
    const int n_i  = m / HW;
    const int hw   = m - n_i * HW;
    const int h    = hw / WDIM;
    const int w    = hw - h * WDIM;
    const size_t abase = ((size_t)n_i * PP + (size_t)h * HP + w);   // (kh=0,kw=0)
    const uint32_t adst0 = s0 + swz(arow, g0);
    const uint32_t adst1 = s0 + swz(arow, g0 + 1);
    const __half* bsrc0 = d_Ww + (size_t)(bn * BN + arow) * KTOT + g0 * 8;
    const uint32_t bdst0 = s0 + A_ST_B + swz(arow, g0);
    const uint32_t bdst1 = s0 + A_ST_B + swz(arow, g0 + 1);

    // ---- compute mapping: 2(M) x 4(N) warps, each 64x32 ----
    const int warp_m = wid >> 2;
    const int warp_n = wid & 3;

    uint32_t aoff[4][2], boff[2][2];
#pragma unroll
    for (int mt = 0; mt < 4; mt++)
#pragma unroll
        for (int ks = 0; ks < 2; ks++) {
            uint32_t row = warp_m * 64 + mt * 16 + (lane & 15);
            uint32_t g   = ks * 2 + (lane >> 4);
            aoff[mt][ks] = swz(row, g);
        }
#pragma unroll
    for (int nt2 = 0; nt2 < 2; nt2++)
#pragma unroll
        for (int ks = 0; ks < 2; ks++) {
            uint32_t row = warp_n * 32 + nt2 * 16 + ((lane >> 4) << 3) + (lane & 7);
            uint32_t g   = ks * 2 + ((lane >> 3) & 1);
            boff[nt2][ks] = A_ST_B + swz(row, g);
        }

    float acc[4][4][4];
#pragma unroll
    for (int i = 0; i < 4; i++)
#pragma unroll
        for (int j = 0; j < 4; j++)
#pragma unroll
            for (int r = 0; r < 4; r++) acc[i][j][r] = 0.f;

    auto issue = [&](int kt, int st) {
        const int tap   = kt >> 3;
        const int kh    = (tap * 11) >> 5;          // tap/3 for 0..8
        const int kw    = tap - 3 * kh;
        const int cbase = (kt & 7) * 32;
        const uint32_t soff = (uint32_t)st * STG_B;
        const __half* ga = d_Xp + (abase + kh * HP + kw) * C_IN + cbase + g0 * 8;
        cp_async16(adst0 + soff, ga);
        cp_async16(adst1 + soff, ga + 8);
        const __half* gb = bsrc0 + kt * BK;
        cp_async16(bdst0 + soff, gb);
        cp_async16(bdst1 + soff, gb + 8);
        asm volatile("cp.async.commit_group;");
    };

    const int ksrot = (wid >> 1) & 1;
    auto compute = [&](int st) {
        const uint32_t soff = (uint32_t)st * STG_B;
#pragma unroll
        for (int ksi = 0; ksi < 2; ksi++) {
            const int ks = ksi ^ ksrot;
            uint32_t a[4][4], b[2][4];
#pragma unroll
            for (int mt = 0; mt < 4; mt++)
                ldmatrix_x4(a[mt][0], a[mt][1], a[mt][2], a[mt][3],
                            s0 + soff + aoff[mt][ks]);
#pragma unroll
            for (int nt2 = 0; nt2 < 2; nt2++)
                ldmatrix_x4(b[nt2][0], b[nt2][1], b[nt2][2], b[nt2][3],
                            s0 + soff + boff[nt2][ks]);
#pragma unroll
            for (int mt = 0; mt < 4; mt++) {
#pragma unroll
                for (int nt = 0; nt < 4; nt++) {
                    uint32_t b0 = b[nt >> 1][(nt & 1) * 2];
                    uint32_t b1 = b[nt >> 1][(nt & 1) * 2 + 1];
                    mma16816(acc[mt][nt], a[mt][0], a[mt][1], a[mt][2], a[mt][3], b0, b1);
                }
            }
        }
    };

    // ---- prologue: fill 4 stages ----
    issue(0, 0);
    issue(1, 1);
    issue(2, 2);
    issue(3, 3);

    // ---- mainloop: per iteration handle chunk pair (kt, kt+1) ----
    const int chswap = wid & 1;
    int st = 0;
#pragma unroll 1
    for (int kt = 0; kt < KCH; kt += 2) {
        asm volatile("cp.async.wait_group 2;" ::: "memory");
        __syncthreads();
        {
            int s4 = st + 4; if (s4 >= NSTAGE) s4 -= NSTAGE;
            int s5 = st + 5; if (s5 >= NSTAGE) s5 -= NSTAGE;
            if (kt + 4 < KCH) issue(kt + 4, s4);
            else asm volatile("cp.async.commit_group;");
            if (kt + 5 < KCH) issue(kt + 5, s5);
            else asm volatile("cp.async.commit_group;");
        }
        {
            int s1 = st + 1; if (s1 >= NSTAGE) s1 -= NSTAGE;
            if (chswap) { compute(s1); compute(st); }
            else        { compute(st); compute(s1); }
        }
        st += 2; if (st >= NSTAGE) st -= NSTAGE;
    }

    // ---- epilogue: out = acc + bias[o] ----
    const int g  = lane >> 2;
    const int qd = (lane & 3) * 2;
#pragma unroll
    for (int mt = 0; mt < 4; mt++) {
#pragma unroll
        for (int hh2 = 0; hh2 < 2; hh2++) {
            const int mloc = warp_m * 64 + mt * 16 + g + 8 * hh2;
            const int mo   = bm * BM + mloc;
            const int n2   = mo / HW;
            const int hw2  = mo - n2 * HW;
            float* op = out + (size_t)n2 * OCH * HW + hw2;
#pragma unroll
            for (int nt = 0; nt < 4; nt++) {
                const int o0 = bn * BN + warp_n * 32 + nt * 8 + qd;
                op[(size_t)o0 * HW]       = acc[mt][nt][hh2 * 2]     + __ldg(&bias[o0]);
                op[(size_t)(o0 + 1) * HW] = acc[mt][nt][hh2 * 2 + 1] + __ldg(&bias[o0 + 1]);
            }
        }
    }
}

// ---------------- launch ----------------
extern "C" void kernel_launch(void* const* d_in, const int* in_sizes, int n_in,
                              void* d_out, int out_size) {
    const float* x      = (const float*)d_in[0];
    const int*   q      = (const int*)  d_in[1];
    const float* wscale = (const float*)d_in[2];
    const float* wmin   = (const float*)d_in[3];
    const float* bias   = (const float*)d_in[4];
    float*       out    = (float*)d_out;

    // 2 launches: fused prep -> mma
    qc_prep<<<XPREP_BLOCKS + WPREP_BLOCKS, 256>>>(x, q, wscale, wmin);

    cudaFuncSetAttribute(qc_mma_kernel,
                         cudaFuncAttributeMaxDynamicSharedMemorySize, SMEM_BYTES);
    dim3 grid(M_TOT / BM, OCH / BN);     // (784, 2)
    qc_mma_kernel<<<grid, NTHREADS, SMEM_BYTES>>>(bias, out);
}